// round 14
// baseline (speedup 1.0000x reference)
#include <cuda_runtime.h>

// Problem constants
#define B_  64
#define S_  512
#define E_  256
#define H_  512
#define V_  50257
#define STR 516     // hs row stride (floats); 16B-aligned rows (516*4=2064)

// Scratch: device globals (the sanctioned allocation-free scratch)
__device__ float g_xproj[S_ * B_ * H_];     // [S][B][H]
__device__ float g_h[2][B_][H_];            // ping-pong hidden state

// ---------------------------------------------------------------------------
// Word fetch: buffer may be int64 (reference dtype) or int32 (JAX x64 off).
// ---------------------------------------------------------------------------
__device__ __forceinline__ int words_is64(const int* w32) {
    return (w32[1] == 0) & (w32[3] == 0) & (w32[5] == 0) & (w32[7] == 0);
}
__device__ __forceinline__ unsigned int word_at(const int* w32, int i, int is64) {
    return is64 ? (unsigned int)w32[2 * i] : (unsigned int)w32[i];
}

// f32x2 helpers --------------------------------------------------------------
__device__ __forceinline__ unsigned long long pack_f32x2(float lo, float hi) {
    unsigned long long v;
    asm("mov.b64 %0, {%1, %2};" : "=l"(v) : "f"(lo), "f"(hi));
    return v;
}
__device__ __forceinline__ void unpack_f32x2(unsigned long long v, float& lo, float& hi) {
    asm("mov.b64 {%0, %1}, %2;" : "=f"(lo), "=f"(hi) : "l"(v));
}

// ---------------------------------------------------------------------------
// Phase A: xproj[s][b][h] = bi[h] + sum_e emb[words[b][s]][e] * Wi[h][e]
// Tiled GEMM 64x64, K=256 in 4 chunks. (Known-good.)
// ---------------------------------------------------------------------------
__global__ __launch_bounds__(256) void xproj_kernel(
    const int* __restrict__ words,
    const float* __restrict__ emb,
    const float* __restrict__ Wi,
    const float* __restrict__ bi)
{
    __shared__ float As[64][65];
    __shared__ float Ws[64][65];
    __shared__ unsigned int wbase[64];

    const int t  = threadIdx.x;
    const int tx = t & 15;
    const int ty = t >> 4;
    const int h0 = blockIdx.x * 64;
    const int m0 = blockIdx.y * 64;

    if (t < 64) {
        int m = m0 + t;
        int s = m >> 6;
        int b = m & 63;            // m = s*64 + b
        int is64 = words_is64(words);
        unsigned int wid = word_at(words, b * S_ + s, is64);
        if (wid >= V_) wid = 0;
        wbase[t] = wid * E_;
    }
    __syncthreads();

    float acc[4][4];
    #pragma unroll
    for (int i = 0; i < 4; i++)
        #pragma unroll
        for (int j = 0; j < 4; j++)
            acc[i][j] = 0.0f;

    for (int ec = 0; ec < 4; ec++) {
        #pragma unroll
        for (int i = 0; i < 16; i++) {
            int idx = t + 256 * i;
            int rr  = idx >> 6;
            int cc  = idx & 63;
            As[rr][cc] = emb[wbase[rr] + ec * 64 + cc];
            Ws[rr][cc] = Wi[(h0 + rr) * E_ + ec * 64 + cc];
        }
        __syncthreads();

        #pragma unroll 8
        for (int e = 0; e < 64; e++) {
            float a0 = As[ty +  0][e];
            float a1 = As[ty + 16][e];
            float a2 = As[ty + 32][e];
            float a3 = As[ty + 48][e];
            float w0 = Ws[tx +  0][e];
            float w1 = Ws[tx + 16][e];
            float w2 = Ws[tx + 32][e];
            float w3 = Ws[tx + 48][e];
            acc[0][0] += a0 * w0; acc[0][1] += a0 * w1; acc[0][2] += a0 * w2; acc[0][3] += a0 * w3;
            acc[1][0] += a1 * w0; acc[1][1] += a1 * w1; acc[1][2] += a1 * w2; acc[1][3] += a1 * w3;
            acc[2][0] += a2 * w0; acc[2][1] += a2 * w1; acc[2][2] += a2 * w2; acc[2][3] += a2 * w3;
            acc[3][0] += a3 * w0; acc[3][1] += a3 * w1; acc[3][2] += a3 * w2; acc[3][3] += a3 * w3;
        }
        __syncthreads();
    }

    #pragma unroll
    for (int i = 0; i < 4; i++) {
        int m = m0 + ty + 16 * i;
        #pragma unroll
        for (int j = 0; j < 4; j++) {
            int h = h0 + tx + 16 * j;
            g_xproj[m * H_ + h] = acc[i][j] + bi[h];
        }
    }
}

// ---------------------------------------------------------------------------
// Phase B: persistent recurrent kernel, HW cluster barriers, f32x2 FMA.
// 128 CTAs = 16 batch-tiles (4 batches) x 8 row-tiles (64 rows); cluster of 8
// = the 8 row-tiles of one batch-tile (the step dependency closes in-cluster).
// 512 threads: thread t -> r = t>>3 (row in tile, 0..63), cb = t&7 (64-col
// chunk). Weights Wh[row, cb*64..+63] pre-packed as 32 u64 f32x2 pairs in regs.
// Per step: cluster wait, stage h[4][512] via __ldcg, 4 batch-slot partial
// dots with fma.rn.f32x2 (slot i holds batch i^(cb&3)), 3-round shfl_xor
// butterfly over the 8-lane group, sigmoid, store, cluster arrive.
// ---------------------------------------------------------------------------
__global__ __launch_bounds__(512, 1) __cluster_dims__(8, 1, 1)
void rnn_kernel(
    const float* __restrict__ Wh,
    const float* __restrict__ bh,
    float* __restrict__ out, int out_size)
{
    __shared__ float hs[4 * STR];    // 8,256 B

    const int t   = threadIdx.x;
    const int cta = blockIdx.x;
    const int bt  = cta >> 3;        // batch tile 0..15 (cluster id)
    const int rt  = cta & 7;         // row tile 0..7    (rank in cluster)
    const int r   = t >> 3;          // 0..63
    const int cb  = t & 7;           // column chunk 0..7
    const int q   = cb & 3;          // batch-slot XOR key
    const int row   = rt * 64 + r;
    const int batch = bt * 4 + q;

    // Pack this thread's 64 Wh weights into 32 f32x2 register pairs
    unsigned long long w64[32];
    {
        const float* wp = &Wh[row * H_ + cb * 64];
        #pragma unroll
        for (int k = 0; k < 32; k++)
            w64[k] = pack_f32x2(wp[2 * k], wp[2 * k + 1]);
    }
    const float bhv = bh[row];

    // Shared-memory byte addresses of the 4 batch-slot bases (32-bit smem window)
    unsigned int sb[4];
    {
        unsigned int hs_base = (unsigned int)__cvta_generic_to_shared(hs);
        #pragma unroll
        for (int i = 0; i < 4; i++)
            sb[i] = hs_base + (unsigned int)(((i ^ q) * STR + cb * 64) * 4);
    }

    for (int s = 0; s < S_; s++) {
        // xproj load issues here — overlaps the cluster-barrier wait below
        float acc0 = bhv + g_xproj[(s * B_ + batch) * H_ + row];

        if (s > 0) {
            asm volatile("barrier.cluster.wait.aligned;" ::: "memory");

            // Stage h (4 batches x 512) from L2, coalesced, 4 floats/thread
            const int par = s & 1;
            #pragma unroll
            for (int i = 0; i < 4; i++) {
                int idx = t + 512 * i;        // 0..2047 over 4x512
                int b   = idx >> 9;
                int c   = idx & 511;
                hs[b * STR + c] = __ldcg(&g_h[par][bt * 4 + b][c]);
            }
            __syncthreads();

            unsigned long long accA[4], accB[4];
            #pragma unroll
            for (int i = 0; i < 4; i++) { accA[i] = 0ull; accB[i] = 0ull; }

            #pragma unroll
            for (int j = 0; j < 16; j++) {
                #pragma unroll
                for (int i = 0; i < 4; i++) {
                    unsigned long long h0, h1;
                    asm volatile("ld.shared.v2.u64 {%0, %1}, [%2];"
                                 : "=l"(h0), "=l"(h1) : "r"(sb[i] + j * 16));
                    asm("fma.rn.f32x2 %0, %1, %2, %0;" : "+l"(accA[i]) : "l"(w64[2 * j]),     "l"(h0));
                    asm("fma.rn.f32x2 %0, %1, %2, %0;" : "+l"(accB[i]) : "l"(w64[2 * j + 1]), "l"(h1));
                }
            }

            float acc[4];
            #pragma unroll
            for (int i = 0; i < 4; i++) {
                float ax, ay, bx, by;
                unpack_f32x2(accA[i], ax, ay);
                unpack_f32x2(accB[i], bx, by);
                acc[i] = (ax + ay) + (bx + by);
            }

            // Butterfly all-reduce over the 8-lane column group.
            // slot i on lane cb = batch i^(cb&3).
            // m=4: partner has same q -> same batch in same slot: plain add.
            {
                float tmp[4];
                #pragma unroll
                for (int i = 0; i < 4; i++)
                    tmp[i] = __shfl_xor_sync(0xffffffffu, acc[i], 4);
                #pragma unroll
                for (int i = 0; i < 4; i++) acc[i] += tmp[i];
                // m=2, m=1: partner lane cb^m holds batch i^q in slot i^m.
                #pragma unroll
                for (int m = 2; m >= 1; m >>= 1) {
                    float tm2[4];
                    #pragma unroll
                    for (int i = 0; i < 4; i++)
                        tm2[i] = __shfl_xor_sync(0xffffffffu, acc[i ^ m], m);
                    #pragma unroll
                    for (int i = 0; i < 4; i++) acc[i] += tm2[i];
                }
            }
            acc0 += acc[0];                    // slot 0 == batch q
        }

        float hv = 1.0f / (1.0f + __expf(-acc0));
        if (cb < 4) {                          // lanes cb and cb+4 duplicate
            g_h[(s + 1) & 1][batch][row] = hv;
            if (s == S_ - 1 && out_size >= B_ + B_ * H_)
                out[B_ + batch * H_ + row] = hv;   // hidden block of output
        }

        // Publish this step (release); matching wait at top of next iteration
        asm volatile("barrier.cluster.arrive.aligned;" ::: "memory");
    }
    asm volatile("barrier.cluster.wait.aligned;" ::: "memory");
}

// ---------------------------------------------------------------------------
// Final head: sig[b] = sigmoid(hidden[b] . Wf[0] + bf[0]).
// Final hidden lives in g_h[0] (parity (511+1)&1 == 0).
// ---------------------------------------------------------------------------
__global__ __launch_bounds__(128) void head_kernel(
    const float* __restrict__ Wf,
    const float* __restrict__ bf,
    float* __restrict__ out)
{
    __shared__ float red[128];
    const int b = blockIdx.x;
    const int t = threadIdx.x;

    float part = 0.0f;
    #pragma unroll
    for (int i = 0; i < 4; i++) {
        int k = t + 128 * i;
        part += g_h[0][b][k] * Wf[k];
    }
    red[t] = part;
    __syncthreads();

    for (int off = 64; off > 0; off >>= 1) {
        if (t < off) red[t] = red[t] + red[t + off];
        __syncthreads();
    }
    if (t == 0)
        out[b] = 1.0f / (1.0f + __expf(-(red[0] + bf[0])));
}

// ---------------------------------------------------------------------------
extern "C" void kernel_launch(void* const* d_in, const int* in_sizes, int n_in,
                              void* d_out, int out_size) {
    const int*   words = (const int*)d_in[0];   // int32 or int64 (auto-detected)
    const float* emb = (const float*)d_in[1];
    const float* Wh  = (const float*)d_in[2];
    const float* bh  = (const float*)d_in[3];
    const float* Wi  = (const float*)d_in[4];
    const float* bi  = (const float*)d_in[5];
    const float* Wf  = (const float*)d_in[6];
    const float* bf  = (const float*)d_in[7];
    float* out = (float*)d_out;

    dim3 gA(H_ / 64, (S_ * B_) / 64);          // (8, 512)
    xproj_kernel<<<gA, 256>>>(words, emb, Wi, bi);

    rnn_kernel<<<128, 512>>>(Wh, bh, out, out_size);

    head_kernel<<<B_, 128>>>(Wf, bf, out);
}

// round 15
// speedup vs baseline: 1.6544x; 1.6544x over previous
#include <cuda_runtime.h>

// Problem constants
#define B_  64
#define S_  512
#define E_  256
#define H_  512
#define V_  50257
#define STR 516     // h row stride (floats); 2064B rows, 16B aligned

// Scratch: device global (the sanctioned allocation-free scratch)
__device__ float g_xproj[S_ * B_ * H_];     // [S][B][H]

// ---------------------------------------------------------------------------
// Word fetch: buffer may be int64 (reference dtype) or int32 (JAX x64 off).
// ---------------------------------------------------------------------------
__device__ __forceinline__ int words_is64(const int* w32) {
    return (w32[1] == 0) & (w32[3] == 0) & (w32[5] == 0) & (w32[7] == 0);
}
__device__ __forceinline__ unsigned int word_at(const int* w32, int i, int is64) {
    return is64 ? (unsigned int)w32[2 * i] : (unsigned int)w32[i];
}

// f32x2 helpers --------------------------------------------------------------
__device__ __forceinline__ unsigned long long pack_f32x2(float lo, float hi) {
    unsigned long long v;
    asm("mov.b64 %0, {%1, %2};" : "=l"(v) : "f"(lo), "f"(hi));
    return v;
}
__device__ __forceinline__ void unpack_f32x2(unsigned long long v, float& lo, float& hi) {
    asm("mov.b64 {%0, %1}, %2;" : "=f"(lo), "=f"(hi) : "l"(v));
}
__device__ __forceinline__ void fma2(unsigned long long& acc,
                                     unsigned long long a, unsigned long long b) {
    asm("fma.rn.f32x2 %0, %1, %2, %0;" : "+l"(acc) : "l"(a), "l"(b));
}

// ---------------------------------------------------------------------------
// Phase A: xproj[s][b][h] = bi[h] + sum_e emb[words[b][s]][e] * Wi[h][e]
// Tiled GEMM 64x64, K=256 in 4 chunks. (Known-good, 414us.)
// ---------------------------------------------------------------------------
__global__ __launch_bounds__(256) void xproj_kernel(
    const int* __restrict__ words,
    const float* __restrict__ emb,
    const float* __restrict__ Wi,
    const float* __restrict__ bi)
{
    __shared__ float As[64][65];
    __shared__ float Ws[64][65];
    __shared__ unsigned int wbase[64];

    const int t  = threadIdx.x;
    const int tx = t & 15;
    const int ty = t >> 4;
    const int h0 = blockIdx.x * 64;
    const int m0 = blockIdx.y * 64;

    if (t < 64) {
        int m = m0 + t;
        int s = m >> 6;
        int b = m & 63;            // m = s*64 + b
        int is64 = words_is64(words);
        unsigned int wid = word_at(words, b * S_ + s, is64);
        if (wid >= V_) wid = 0;
        wbase[t] = wid * E_;
    }
    __syncthreads();

    float acc[4][4];
    #pragma unroll
    for (int i = 0; i < 4; i++)
        #pragma unroll
        for (int j = 0; j < 4; j++)
            acc[i][j] = 0.0f;

    for (int ec = 0; ec < 4; ec++) {
        #pragma unroll
        for (int i = 0; i < 16; i++) {
            int idx = t + 256 * i;
            int rr  = idx >> 6;
            int cc  = idx & 63;
            As[rr][cc] = emb[wbase[rr] + ec * 64 + cc];
            Ws[rr][cc] = Wi[(h0 + rr) * E_ + ec * 64 + cc];
        }
        __syncthreads();

        #pragma unroll 8
        for (int e = 0; e < 64; e++) {
            float a0 = As[ty +  0][e];
            float a1 = As[ty + 16][e];
            float a2 = As[ty + 32][e];
            float a3 = As[ty + 48][e];
            float w0 = Ws[tx +  0][e];
            float w1 = Ws[tx + 16][e];
            float w2 = Ws[tx + 32][e];
            float w3 = Ws[tx + 48][e];
            acc[0][0] += a0 * w0; acc[0][1] += a0 * w1; acc[0][2] += a0 * w2; acc[0][3] += a0 * w3;
            acc[1][0] += a1 * w0; acc[1][1] += a1 * w1; acc[1][2] += a1 * w2; acc[1][3] += a1 * w3;
            acc[2][0] += a2 * w0; acc[2][1] += a2 * w1; acc[2][2] += a2 * w2; acc[2][3] += a2 * w3;
            acc[3][0] += a3 * w0; acc[3][1] += a3 * w1; acc[3][2] += a3 * w2; acc[3][3] += a3 * w3;
        }
        __syncthreads();
    }

    #pragma unroll
    for (int i = 0; i < 4; i++) {
        int m = m0 + ty + 16 * i;
        #pragma unroll
        for (int j = 0; j < 4; j++) {
            int h = h0 + tx + 16 * j;
            g_xproj[m * H_ + h] = acc[i][j] + bi[h];
        }
    }
}

// ---------------------------------------------------------------------------
// Phase B: persistent recurrent kernel. Cluster-8, DSMEM h-exchange, f32x2.
// 128 CTAs = 16 clusters (4 batches each) x 8 row-tile CTAs (64 rows each).
// Thread t (256/CTA): r = t>>2 (row in tile), cb = t&3 (128-col chunk & batch).
// Weights Wh[row, cb*128 .. +127] pre-packed as 64 u64 f32x2 pairs in regs.
// Per step:
//   prefetch xproj -> cluster wait -> dot via fma.rn.f32x2 over smem h
//   (slot i = batch i^cb; LDS.128 conflict-free) -> 2-round shfl_xor butterfly
//   -> sigmoid -> push own h value into ALL 8 CTAs' smem (mapa + st.cluster,
//   double-buffered) -> cluster arrive (release covers DSMEM stores).
// No global h traffic at all. Head computed in-kernel by rank-0 CTAs.
// ---------------------------------------------------------------------------
__global__ __launch_bounds__(256, 1) __cluster_dims__(8, 1, 1)
void rnn_kernel(
    const float* __restrict__ Wh,
    const float* __restrict__ bh,
    const float* __restrict__ Wf,
    const float* __restrict__ bf,
    float* __restrict__ out, int out_size)
{
    __shared__ float hbuf[2][4 * STR];   // 16,512 B: [parity][batch-slot][row 0..511]
    __shared__ float red[256];

    const int t   = threadIdx.x;
    const int cta = blockIdx.x;
    const int bt  = cta >> 3;        // cluster id 0..15 (batch tile of 4)
    const int rt  = cta & 7;         // rank in cluster = row tile 0..7
    const int r   = t >> 2;          // 0..63
    const int cb  = t & 3;           // column chunk AND batch slot 0..3
    const int row   = rt * 64 + r;
    const int batch = bt * 4 + cb;

    // Pack this thread's 128 Wh weights into 64 f32x2 register pairs
    unsigned long long w64[64];
    {
        const float* wp = &Wh[row * H_ + cb * 128];
        #pragma unroll
        for (int k = 0; k < 64; k++)
            w64[k] = pack_f32x2(wp[2 * k], wp[2 * k + 1]);
    }
    const float bhv = bh[row];

    // DSMEM destination (my h value's slot) in each parity buffer
    const unsigned int my_dst0 =
        (unsigned int)__cvta_generic_to_shared(&hbuf[0][cb * STR + row]);
    const unsigned int my_dst1 =
        (unsigned int)__cvta_generic_to_shared(&hbuf[1][cb * STR + row]);

    for (int s = 0; s < S_; s++) {
        // xproj load issues here — overlaps the cluster-barrier wait below
        float acc0 = bhv + g_xproj[(s * B_ + batch) * H_ + row];

        if (s > 0) {
            asm volatile("barrier.cluster.wait.aligned;" ::: "memory");

            const float* hb = hbuf[s & 1];
            unsigned long long aE[4], aO[4];
            #pragma unroll
            for (int i = 0; i < 4; i++) { aE[i] = 0ull; aO[i] = 0ull; }

            #pragma unroll
            for (int j = 0; j < 32; j++) {        // 128 floats = 32 x float4
                #pragma unroll
                for (int i = 0; i < 4; i++) {
                    // plain (schedulable) LDS.128: two packed f32x2 values
                    const ulonglong2 h2 = *(const ulonglong2*)
                        &hb[(i ^ cb) * STR + cb * 128 + j * 4];
                    fma2(aE[i], w64[2 * j],     h2.x);
                    fma2(aO[i], w64[2 * j + 1], h2.y);
                }
            }

            float acc[4];
            #pragma unroll
            for (int i = 0; i < 4; i++) {
                float ex, ey, ox, oy;
                unpack_f32x2(aE[i], ex, ey);
                unpack_f32x2(aO[i], ox, oy);
                acc[i] = (ex + ey) + (ox + oy);
            }

            // Butterfly all-reduce over the 4-lane column group:
            // partner lane cb^m holds batch i^cb in slot i^m.
            #pragma unroll
            for (int m = 2; m >= 1; m >>= 1) {
                float tmp[4];
                #pragma unroll
                for (int i = 0; i < 4; i++)
                    tmp[i] = __shfl_xor_sync(0xffffffffu, acc[i ^ m], m);
                #pragma unroll
                for (int i = 0; i < 4; i++) acc[i] += tmp[i];
            }
            acc0 += acc[0];                    // slot 0 == batch cb
        }

        float hv = 1.0f / (1.0f + __expf(-acc0));

        // Push my h value into all 8 CTAs' smem (incl. own), next-parity buffer
        {
            unsigned int dst = ((s + 1) & 1) ? my_dst1 : my_dst0;
            #pragma unroll
            for (int rk = 0; rk < 8; rk++) {
                unsigned int ra;
                asm volatile("mapa.shared::cluster.u32 %0, %1, %2;"
                             : "=r"(ra) : "r"(dst), "r"(rk));
                asm volatile("st.shared::cluster.f32 [%0], %1;"
                             :: "r"(ra), "f"(hv) : "memory");
            }
        }
        if (s == S_ - 1 && out_size >= B_ + B_ * H_)
            out[B_ + batch * H_ + row] = hv;   // hidden block of the output

        // Release: DSMEM stores visible to peers after their wait
        asm volatile("barrier.cluster.arrive.aligned;" ::: "memory");
    }
    asm volatile("barrier.cluster.wait.aligned;" ::: "memory");

    // Head: sig[b] = sigmoid(hidden[b] . Wf[0] + bf[0]); final h is in hbuf[0]
    if (rt == 0) {
        float part = 0.0f;
        #pragma unroll
        for (int m = 0; m < 8; m++) {
            int k = r + 64 * m;
            part += hbuf[0][cb * STR + k] * Wf[k];
        }
        red[t] = part;                         // t = r*4 + cb
        __syncthreads();
        for (int off = 32; off > 0; off >>= 1) {
            if (r < off) red[r * 4 + cb] += red[(r + off) * 4 + cb];
            __syncthreads();
        }
        if (r == 0)
            out[batch] = 1.0f / (1.0f + __expf(-(red[cb] + bf[0])));
    }
}

// ---------------------------------------------------------------------------
extern "C" void kernel_launch(void* const* d_in, const int* in_sizes, int n_in,
                              void* d_out, int out_size) {
    const int*   words = (const int*)d_in[0];   // int32 or int64 (auto-detected)
    const float* emb = (const float*)d_in[1];
    const float* Wh  = (const float*)d_in[2];
    const float* bh  = (const float*)d_in[3];
    const float* Wi  = (const float*)d_in[4];
    const float* bi  = (const float*)d_in[5];
    const float* Wf  = (const float*)d_in[6];
    const float* bf  = (const float*)d_in[7];
    float* out = (float*)d_out;

    dim3 gA(H_ / 64, (S_ * B_) / 64);          // (8, 512)
    xproj_kernel<<<gA, 256>>>(words, emb, Wi, bi);

    rnn_kernel<<<128, 256>>>(Wh, bh, Wf, bf, out, out_size);
}

// round 16
// speedup vs baseline: 1.8186x; 1.0992x over previous
#include <cuda_runtime.h>

// Problem constants
#define B_  64
#define S_  512
#define E_  256
#define H_  512
#define V_  50257
#define STR 516     // h row stride (floats); 2064B rows, 16B aligned

// Scratch: device global (the sanctioned allocation-free scratch)
__device__ float g_xproj[S_ * B_ * H_];     // [S][B][H]

// ---------------------------------------------------------------------------
// Word fetch: buffer may be int64 (reference dtype) or int32 (JAX x64 off).
// ---------------------------------------------------------------------------
__device__ __forceinline__ int words_is64(const int* w32) {
    return (w32[1] == 0) & (w32[3] == 0) & (w32[5] == 0) & (w32[7] == 0);
}
__device__ __forceinline__ unsigned int word_at(const int* w32, int i, int is64) {
    return is64 ? (unsigned int)w32[2 * i] : (unsigned int)w32[i];
}

// f32x2 helpers --------------------------------------------------------------
__device__ __forceinline__ unsigned long long pack_f32x2(float lo, float hi) {
    unsigned long long v;
    asm("mov.b64 %0, {%1, %2};" : "=l"(v) : "f"(lo), "f"(hi));
    return v;
}
__device__ __forceinline__ void unpack_f32x2(unsigned long long v, float& lo, float& hi) {
    asm("mov.b64 {%0, %1}, %2;" : "=f"(lo), "=f"(hi) : "l"(v));
}
__device__ __forceinline__ void fma2(unsigned long long& acc,
                                     unsigned long long a, unsigned long long b) {
    asm("fma.rn.f32x2 %0, %1, %2, %0;" : "+l"(acc) : "l"(a), "l"(b));
}

// mbarrier helpers -----------------------------------------------------------
__device__ __forceinline__ void mbar_init(unsigned int mb, unsigned int count) {
    asm volatile("mbarrier.init.shared.b64 [%0], %1;" :: "r"(mb), "r"(count) : "memory");
}
__device__ __forceinline__ void mbar_expect(unsigned int mb, unsigned int bytes) {
    asm volatile("mbarrier.arrive.expect_tx.shared.b64 _, [%0], %1;"
                 :: "r"(mb), "r"(bytes) : "memory");
}
__device__ __forceinline__ void mbar_wait(unsigned int mb, int phase) {
    unsigned int done;
    asm volatile(
        "{\n\t.reg .pred p;\n\t"
        "mbarrier.try_wait.parity.acquire.cluster.shared::cta.b64 p, [%1], %2;\n\t"
        "selp.b32 %0, 1, 0, p;\n\t}"
        : "=r"(done) : "r"(mb), "r"(phase) : "memory");
    while (!done) {
        asm volatile(
            "{\n\t.reg .pred p;\n\t"
            "mbarrier.try_wait.parity.acquire.cluster.shared::cta.b64 p, [%1], %2, 0x989680;\n\t"
            "selp.b32 %0, 1, 0, p;\n\t}"
            : "=r"(done) : "r"(mb), "r"(phase) : "memory");
    }
}
// st.async: remote smem store that also signals the remote mbarrier (tx bytes)
__device__ __forceinline__ void st_async_f32(unsigned int raddr, float v, unsigned int rmbar) {
    asm volatile("st.async.weak.shared::cluster.mbarrier::complete_tx::bytes.b32 [%0], %1, [%2];"
                 :: "r"(raddr), "r"(__float_as_uint(v)), "r"(rmbar) : "memory");
}

// ---------------------------------------------------------------------------
// Phase A: xproj[s][b][h] = bi[h] + sum_e emb[words[b][s]][e] * Wi[h][e]
// Tiled GEMM 64x64, K=256 in 4 chunks. (Known-good, ~414us.)
// ---------------------------------------------------------------------------
__global__ __launch_bounds__(256) void xproj_kernel(
    const int* __restrict__ words,
    const float* __restrict__ emb,
    const float* __restrict__ Wi,
    const float* __restrict__ bi)
{
    __shared__ float As[64][65];
    __shared__ float Ws[64][65];
    __shared__ unsigned int wbase[64];

    const int t  = threadIdx.x;
    const int tx = t & 15;
    const int ty = t >> 4;
    const int h0 = blockIdx.x * 64;
    const int m0 = blockIdx.y * 64;

    if (t < 64) {
        int m = m0 + t;
        int s = m >> 6;
        int b = m & 63;            // m = s*64 + b
        int is64 = words_is64(words);
        unsigned int wid = word_at(words, b * S_ + s, is64);
        if (wid >= V_) wid = 0;
        wbase[t] = wid * E_;
    }
    __syncthreads();

    float acc[4][4];
    #pragma unroll
    for (int i = 0; i < 4; i++)
        #pragma unroll
        for (int j = 0; j < 4; j++)
            acc[i][j] = 0.0f;

    for (int ec = 0; ec < 4; ec++) {
        #pragma unroll
        for (int i = 0; i < 16; i++) {
            int idx = t + 256 * i;
            int rr  = idx >> 6;
            int cc  = idx & 63;
            As[rr][cc] = emb[wbase[rr] + ec * 64 + cc];
            Ws[rr][cc] = Wi[(h0 + rr) * E_ + ec * 64 + cc];
        }
        __syncthreads();

        #pragma unroll 8
        for (int e = 0; e < 64; e++) {
            float a0 = As[ty +  0][e];
            float a1 = As[ty + 16][e];
            float a2 = As[ty + 32][e];
            float a3 = As[ty + 48][e];
            float w0 = Ws[tx +  0][e];
            float w1 = Ws[tx + 16][e];
            float w2 = Ws[tx + 32][e];
            float w3 = Ws[tx + 48][e];
            acc[0][0] += a0 * w0; acc[0][1] += a0 * w1; acc[0][2] += a0 * w2; acc[0][3] += a0 * w3;
            acc[1][0] += a1 * w0; acc[1][1] += a1 * w1; acc[1][2] += a1 * w2; acc[1][3] += a1 * w3;
            acc[2][0] += a2 * w0; acc[2][1] += a2 * w1; acc[2][2] += a2 * w2; acc[2][3] += a2 * w3;
            acc[3][0] += a3 * w0; acc[3][1] += a3 * w1; acc[3][2] += a3 * w2; acc[3][3] += a3 * w3;
        }
        __syncthreads();
    }

    #pragma unroll
    for (int i = 0; i < 4; i++) {
        int m = m0 + ty + 16 * i;
        #pragma unroll
        for (int j = 0; j < 4; j++) {
            int h = h0 + tx + 16 * j;
            g_xproj[m * H_ + h] = acc[i][j] + bi[h];
        }
    }
}

// ---------------------------------------------------------------------------
// Phase B: persistent recurrent kernel. Cluster-8, st.async + mbarrier sync.
// 128 CTAs = 16 clusters (4 batches) x 8 row-tile CTAs (64 rows each).
// Thread t (256): r = t>>2 (row in tile), cb = t&3 (128-col chunk & batch).
// Weights pre-packed as 64 u64 f32x2 pairs in regs (R15 compute core).
// Sync: NO cluster barrier in the loop. Each thread st.async-pushes its h
// value to all 8 CTAs' hbuf (next parity) — the stores themselves complete
// the consumers' mbarrier (8192 tx bytes/phase). Consumers wake via
// try_wait.parity. expect_tx re-arm is race-free: remote phase-(s+2) stores
// are gated on my step-s delivery, which includes tid0's store, issued after
// tid0's re-arm.
// ---------------------------------------------------------------------------
__global__ __launch_bounds__(256, 1) __cluster_dims__(8, 1, 1)
void rnn_kernel(
    const float* __restrict__ Wh,
    const float* __restrict__ bh,
    const float* __restrict__ Wf,
    const float* __restrict__ bf,
    float* __restrict__ out, int out_size)
{
    __shared__ float hbuf[2][4 * STR];          // 16,512 B
    __shared__ alignas(8) unsigned long long mbar[2];
    __shared__ float red[256];

    const int t   = threadIdx.x;
    const int cta = blockIdx.x;
    const int bt  = cta >> 3;        // cluster id 0..15 (batch tile of 4)
    const int rt  = cta & 7;         // rank in cluster = row tile 0..7
    const int r   = t >> 2;          // 0..63
    const int cb  = t & 3;           // column chunk AND batch slot 0..3
    const int row   = rt * 64 + r;
    const int batch = bt * 4 + cb;

    const unsigned int mb0 = (unsigned int)__cvta_generic_to_shared(&mbar[0]);
    const unsigned int mb1 = (unsigned int)__cvta_generic_to_shared(&mbar[1]);

    // Init mbarriers + pre-arm phase 0 of both parities BEFORE cluster.sync,
    // so no st.async can beat the expect_tx.
    if (t == 0) {
        mbar_init(mb0, 1);
        mbar_init(mb1, 1);
        mbar_expect(mb0, 8192);
        mbar_expect(mb1, 8192);
    }
    __syncthreads();
    asm volatile("barrier.cluster.arrive.aligned;" ::: "memory");
    asm volatile("barrier.cluster.wait.aligned;"   ::: "memory");

    // Pack this thread's 128 Wh weights into 64 f32x2 register pairs
    unsigned long long w64[64];
    {
        const float* wp = &Wh[row * H_ + cb * 128];
        #pragma unroll
        for (int k = 0; k < 64; k++)
            w64[k] = pack_f32x2(wp[2 * k], wp[2 * k + 1]);
    }
    const float bhv = bh[row];

    // My h value's slot in each parity buffer (local smem address)
    const unsigned int my_dst0 =
        (unsigned int)__cvta_generic_to_shared(&hbuf[0][cb * STR + row]);
    const unsigned int my_dst1 =
        (unsigned int)__cvta_generic_to_shared(&hbuf[1][cb * STR + row]);

    for (int s = 0; s < S_; s++) {
        // xproj load issues here — overlaps the mbarrier wait below
        float acc0 = bhv + g_xproj[(s * B_ + batch) * H_ + row];

        if (s > 0) {
            const unsigned int mb = (s & 1) ? mb1 : mb0;
            const int phase = ((s >> 1) + (s & 1) + 1) & 1;
            mbar_wait(mb, phase);
            if (t == 0) mbar_expect(mb, 8192);   // re-arm for step s+2

            const float* hb = hbuf[s & 1];
            unsigned long long aE[4], aO[4];
            #pragma unroll
            for (int i = 0; i < 4; i++) { aE[i] = 0ull; aO[i] = 0ull; }

            #pragma unroll
            for (int j = 0; j < 32; j++) {        // 128 floats = 32 x float4
                #pragma unroll
                for (int i = 0; i < 4; i++) {
                    const ulonglong2 h2 = *(const ulonglong2*)
                        &hb[(i ^ cb) * STR + cb * 128 + j * 4];
                    fma2(aE[i], w64[2 * j],     h2.x);
                    fma2(aO[i], w64[2 * j + 1], h2.y);
                }
            }

            float acc[4];
            #pragma unroll
            for (int i = 0; i < 4; i++) {
                float ex, ey, ox, oy;
                unpack_f32x2(aE[i], ex, ey);
                unpack_f32x2(aO[i], ox, oy);
                acc[i] = (ex + ey) + (ox + oy);
            }

            // Butterfly all-reduce over the 4-lane column group:
            // partner lane cb^m holds batch i^cb in slot i^m.
            #pragma unroll
            for (int m = 2; m >= 1; m >>= 1) {
                float tmp[4];
                #pragma unroll
                for (int i = 0; i < 4; i++)
                    tmp[i] = __shfl_xor_sync(0xffffffffu, acc[i ^ m], m);
                #pragma unroll
                for (int i = 0; i < 4; i++) acc[i] += tmp[i];
            }
            acc0 += acc[0];                    // slot 0 == batch cb
        }

        float hv = 1.0f / (1.0f + __expf(-acc0));

        // Push my h value into all 8 CTAs' next-parity buffer; each store
        // also delivers 4 tx bytes to that CTA's next-parity mbarrier.
        {
            const unsigned int dst  = ((s + 1) & 1) ? my_dst1 : my_dst0;
            const unsigned int mbp  = ((s + 1) & 1) ? mb1 : mb0;
            #pragma unroll
            for (int rk = 0; rk < 8; rk++) {
                unsigned int ra, rm;
                asm volatile("mapa.shared::cluster.u32 %0, %1, %2;"
                             : "=r"(ra) : "r"(dst), "r"(rk));
                asm volatile("mapa.shared::cluster.u32 %0, %1, %2;"
                             : "=r"(rm) : "r"(mbp), "r"(rk));
                st_async_f32(ra, hv, rm);
            }
        }
        if (s == S_ - 1 && out_size >= B_ + B_ * H_)
            out[B_ + batch * H_ + row] = hv;   // hidden block of the output
    }

    // Final delivery (step 511 data, parity 0): phase((512>>1)+0+1)&1 = 1.
    // All CTAs wait so nobody exits with in-flight incoming stores.
    mbar_wait(mb0, 1);

    // Head: sig[b] = sigmoid(hidden[b] . Wf[0] + bf[0]); final h in hbuf[0]
    if (rt == 0) {
        float part = 0.0f;
        #pragma unroll
        for (int m = 0; m < 8; m++) {
            int k = r + 64 * m;
            part += hbuf[0][cb * STR + k] * Wf[k];
        }
        red[t] = part;                         // t = r*4 + cb
        __syncthreads();
        for (int off = 32; off > 0; off >>= 1) {
            if (r < off) red[r * 4 + cb] += red[(r + off) * 4 + cb];
            __syncthreads();
        }
        if (r == 0)
            out[batch] = 1.0f / (1.0f + __expf(-(red[cb] + bf[0])));
    }
}

// ---------------------------------------------------------------------------
extern "C" void kernel_launch(void* const* d_in, const int* in_sizes, int n_in,
                              void* d_out, int out_size) {
    const int*   words = (const int*)d_in[0];   // int32 or int64 (auto-detected)
    const float* emb = (const float*)d_in[1];
    const float* Wh  = (const float*)d_in[2];
    const float* bh  = (const float*)d_in[3];
    const float* Wi  = (const float*)d_in[4];
    const float* bi  = (const float*)d_in[5];
    const float* Wf  = (const float*)d_in[6];
    const float* bf  = (const float*)d_in[7];
    float* out = (float*)d_out;

    dim3 gA(H_ / 64, (S_ * B_) / 64);          // (8, 512)
    xproj_kernel<<<gA, 256>>>(words, emb, Wi, bi);

    rnn_kernel<<<128, 256>>>(Wh, bh, Wf, bf, out, out_size);
}

// round 17
// speedup vs baseline: 1.9124x; 1.0516x over previous
#include <cuda_runtime.h>

// Problem constants
#define B_  64
#define S_  512
#define E_  256
#define H_  512
#define V_  50257
#define RBLK 260    // per-source-rank block stride in hbuf (floats); 1040B, 16B aligned
                    // 260 mod 128-float wrap gives bank offsets {0,72,16,88}/{64,8,80,24}
                    // across the 4-lane group -> conflict-free LDS.128

// Scratch: device global (the sanctioned allocation-free scratch)
__device__ float g_xproj[S_ * B_ * H_];     // [S][B][H]

// ---------------------------------------------------------------------------
// Word fetch: buffer may be int64 (reference dtype) or int32 (JAX x64 off).
// ---------------------------------------------------------------------------
__device__ __forceinline__ int words_is64(const int* w32) {
    return (w32[1] == 0) & (w32[3] == 0) & (w32[5] == 0) & (w32[7] == 0);
}
__device__ __forceinline__ unsigned int word_at(const int* w32, int i, int is64) {
    return is64 ? (unsigned int)w32[2 * i] : (unsigned int)w32[i];
}

// f32x2 helpers --------------------------------------------------------------
__device__ __forceinline__ unsigned long long pack_f32x2(float lo, float hi) {
    unsigned long long v;
    asm("mov.b64 %0, {%1, %2};" : "=l"(v) : "f"(lo), "f"(hi));
    return v;
}
__device__ __forceinline__ void unpack_f32x2(unsigned long long v, float& lo, float& hi) {
    asm("mov.b64 {%0, %1}, %2;" : "=f"(lo), "=f"(hi) : "l"(v));
}
__device__ __forceinline__ void fma2(unsigned long long& acc,
                                     unsigned long long a, unsigned long long b) {
    asm("fma.rn.f32x2 %0, %1, %2, %0;" : "+l"(acc) : "l"(a), "l"(b));
}

// mbarrier helpers -----------------------------------------------------------
__device__ __forceinline__ void mbar_init(unsigned int mb, unsigned int count) {
    asm volatile("mbarrier.init.shared.b64 [%0], %1;" :: "r"(mb), "r"(count) : "memory");
}
__device__ __forceinline__ void mbar_expect(unsigned int mb, unsigned int bytes) {
    asm volatile("mbarrier.arrive.expect_tx.shared.b64 _, [%0], %1;"
                 :: "r"(mb), "r"(bytes) : "memory");
}
__device__ __forceinline__ void mbar_wait(unsigned int mb, int phase) {
    unsigned int done;
    asm volatile(
        "{\n\t.reg .pred p;\n\t"
        "mbarrier.try_wait.parity.acquire.cluster.shared::cta.b64 p, [%1], %2;\n\t"
        "selp.b32 %0, 1, 0, p;\n\t}"
        : "=r"(done) : "r"(mb), "r"(phase) : "memory");
    while (!done) {
        asm volatile(
            "{\n\t.reg .pred p;\n\t"
            "mbarrier.try_wait.parity.acquire.cluster.shared::cta.b64 p, [%1], %2, 0x989680;\n\t"
            "selp.b32 %0, 1, 0, p;\n\t}"
            : "=r"(done) : "r"(mb), "r"(phase) : "memory");
    }
}

// ---------------------------------------------------------------------------
// Phase A: xproj[s][b][h] = bi[h] + sum_e emb[words[b][s]][e] * Wi[h][e]
// Tiled GEMM 64x64, K=256 in 4 chunks. (Known-good, ~414us.)
// ---------------------------------------------------------------------------
__global__ __launch_bounds__(256) void xproj_kernel(
    const int* __restrict__ words,
    const float* __restrict__ emb,
    const float* __restrict__ Wi,
    const float* __restrict__ bi)
{
    __shared__ float As[64][65];
    __shared__ float Ws[64][65];
    __shared__ unsigned int wbase[64];

    const int t  = threadIdx.x;
    const int tx = t & 15;
    const int ty = t >> 4;
    const int h0 = blockIdx.x * 64;
    const int m0 = blockIdx.y * 64;

    if (t < 64) {
        int m = m0 + t;
        int s = m >> 6;
        int b = m & 63;            // m = s*64 + b
        int is64 = words_is64(words);
        unsigned int wid = word_at(words, b * S_ + s, is64);
        if (wid >= V_) wid = 0;
        wbase[t] = wid * E_;
    }
    __syncthreads();

    float acc[4][4];
    #pragma unroll
    for (int i = 0; i < 4; i++)
        #pragma unroll
        for (int j = 0; j < 4; j++)
            acc[i][j] = 0.0f;

    for (int ec = 0; ec < 4; ec++) {
        #pragma unroll
        for (int i = 0; i < 16; i++) {
            int idx = t + 256 * i;
            int rr  = idx >> 6;
            int cc  = idx & 63;
            As[rr][cc] = emb[wbase[rr] + ec * 64 + cc];
            Ws[rr][cc] = Wi[(h0 + rr) * E_ + ec * 64 + cc];
        }
        __syncthreads();

        #pragma unroll 8
        for (int e = 0; e < 64; e++) {
            float a0 = As[ty +  0][e];
            float a1 = As[ty + 16][e];
            float a2 = As[ty + 32][e];
            float a3 = As[ty + 48][e];
            float w0 = Ws[tx +  0][e];
            float w1 = Ws[tx + 16][e];
            float w2 = Ws[tx + 32][e];
            float w3 = Ws[tx + 48][e];
            acc[0][0] += a0 * w0; acc[0][1] += a0 * w1; acc[0][2] += a0 * w2; acc[0][3] += a0 * w3;
            acc[1][0] += a1 * w0; acc[1][1] += a1 * w1; acc[1][2] += a1 * w2; acc[1][3] += a1 * w3;
            acc[2][0] += a2 * w0; acc[2][1] += a2 * w1; acc[2][2] += a2 * w2; acc[2][3] += a2 * w3;
            acc[3][0] += a3 * w0; acc[3][1] += a3 * w1; acc[3][2] += a3 * w2; acc[3][3] += a3 * w3;
        }
        __syncthreads();
    }

    #pragma unroll
    for (int i = 0; i < 4; i++) {
        int m = m0 + ty + 16 * i;
        #pragma unroll
        for (int j = 0; j < 4; j++) {
            int h = h0 + tx + 16 * j;
            g_xproj[m * H_ + h] = acc[i][j] + bi[h];
        }
    }
}

// ---------------------------------------------------------------------------
// Phase B: persistent recurrent kernel. Cluster-8, BULK h-exchange.
// 128 CTAs = 16 clusters (4 batches) x 8 row-tile CTAs (64 rows each).
// Thread t (256): r = t>>2 (row in tile), cb = t&3 (128-col chunk & batch).
// Weights pre-packed as 64 u64 f32x2 pairs in regs (R16 compute core).
// Exchange per step: write h into 1KB local staging (double-buffered) ->
// syncthreads -> fence.proxy.async -> tids 0..7 each issue ONE
// cp.async.bulk (1040B) to rank t's hbuf block + remote mbarrier complete_tx.
// Consumer mbarrier sees 8 arrivals/step (was 2048). hbuf layout is
// per-source-rank blocks of RBLK floats: h[batch slot i][row rk*64+rr]
// lives at hbuf[p][rk*RBLK + i*64 + rr].
// ---------------------------------------------------------------------------
__global__ __launch_bounds__(256, 1) __cluster_dims__(8, 1, 1)
void rnn_kernel(
    const float* __restrict__ Wh,
    const float* __restrict__ bh,
    const float* __restrict__ Wf,
    const float* __restrict__ bf,
    float* __restrict__ out, int out_size)
{
    __shared__ alignas(16) float hbuf[2][8 * RBLK];   // 16,640 B
    __shared__ alignas(16) float stg[2][RBLK];        //  2,080 B
    __shared__ alignas(8)  unsigned long long mbar[2];
    __shared__ float red[256];

    const int t   = threadIdx.x;
    const int cta = blockIdx.x;
    const int bt  = cta >> 3;        // cluster id 0..15 (batch tile of 4)
    const int rt  = cta & 7;         // rank in cluster = row tile 0..7
    const int r   = t >> 2;          // 0..63
    const int cb  = t & 3;           // column chunk AND batch slot 0..3
    const int row   = rt * 64 + r;
    const int batch = bt * 4 + cb;

    const unsigned int mb0 = (unsigned int)__cvta_generic_to_shared(&mbar[0]);
    const unsigned int mb1 = (unsigned int)__cvta_generic_to_shared(&mbar[1]);

    // Init mbarriers + pre-arm both parities BEFORE cluster.sync.
    if (t == 0) {
        mbar_init(mb0, 1);
        mbar_init(mb1, 1);
        mbar_expect(mb0, 8 * RBLK * 4);
        mbar_expect(mb1, 8 * RBLK * 4);
    }
    __syncthreads();
    asm volatile("barrier.cluster.arrive.aligned;" ::: "memory");
    asm volatile("barrier.cluster.wait.aligned;"   ::: "memory");

    // Pack this thread's 128 Wh weights into 64 f32x2 register pairs
    unsigned long long w64[64];
    {
        const float* wp = &Wh[row * H_ + cb * 128];
        #pragma unroll
        for (int k = 0; k < 64; k++)
            w64[k] = pack_f32x2(wp[2 * k], wp[2 * k + 1]);
    }
    const float bhv = bh[row];

    // Local staging addresses + my hbuf block offset (same in every CTA)
    const unsigned int stg0 = (unsigned int)__cvta_generic_to_shared(&stg[0][0]);
    const unsigned int stg1 = (unsigned int)__cvta_generic_to_shared(&stg[1][0]);
    const unsigned int dst0 = (unsigned int)__cvta_generic_to_shared(&hbuf[0][rt * RBLK]);
    const unsigned int dst1 = (unsigned int)__cvta_generic_to_shared(&hbuf[1][rt * RBLK]);

    for (int s = 0; s < S_; s++) {
        // xproj load issues here — overlaps the mbarrier wait below
        float acc0 = bhv + g_xproj[(s * B_ + batch) * H_ + row];

        if (s > 0) {
            const unsigned int mb = (s & 1) ? mb1 : mb0;
            const int phase = ((s >> 1) + (s & 1) + 1) & 1;
            mbar_wait(mb, phase);
            if (t == 0) mbar_expect(mb, 8 * RBLK * 4);   // re-arm for step s+2

            const float* hb = hbuf[s & 1];
            unsigned long long aE[4], aO[4];
            #pragma unroll
            for (int i = 0; i < 4; i++) { aE[i] = 0ull; aO[i] = 0ull; }

            #pragma unroll
            for (int j = 0; j < 32; j++) {
                const int blk = cb * 2 + (j >> 4);        // source-rank block
                const int c   = (j & 15) * 4;             // col within block
                #pragma unroll
                for (int i = 0; i < 4; i++) {
                    const ulonglong2 h2 = *(const ulonglong2*)
                        &hb[blk * RBLK + (i ^ cb) * 64 + c];
                    fma2(aE[i], w64[2 * j],     h2.x);
                    fma2(aO[i], w64[2 * j + 1], h2.y);
                }
            }

            float acc[4];
            #pragma unroll
            for (int i = 0; i < 4; i++) {
                float ex, ey, ox, oy;
                unpack_f32x2(aE[i], ex, ey);
                unpack_f32x2(aO[i], ox, oy);
                acc[i] = (ex + ey) + (ox + oy);
            }

            // Butterfly all-reduce over the 4-lane column group:
            // partner lane cb^m holds batch i^cb in slot i^m.
            #pragma unroll
            for (int m = 2; m >= 1; m >>= 1) {
                float tmp[4];
                #pragma unroll
                for (int i = 0; i < 4; i++)
                    tmp[i] = __shfl_xor_sync(0xffffffffu, acc[i ^ m], m);
                #pragma unroll
                for (int i = 0; i < 4; i++) acc[i] += tmp[i];
            }
            acc0 += acc[0];                    // slot 0 == batch cb
        }

        float hv = 1.0f / (1.0f + __expf(-acc0));

        const int p = (s + 1) & 1;             // parity of outgoing data
        // Source-read protection: allow 1 outstanding bulk group; the group
        // committed 2 steps ago (same staging parity) must be read-complete.
        if (t < 8)
            asm volatile("cp.async.bulk.wait_group.read 1;" ::: "memory");
        __syncthreads();                       // wait_group -> staging writes

        stg[p][cb * 64 + r] = hv;              // my value into local staging
        __syncthreads();                       // staging writes -> bulk copy

        if (t < 8) {
            asm volatile("fence.proxy.async.shared::cta;" ::: "memory");
            const unsigned int src = p ? stg1 : stg0;
            const unsigned int dl  = p ? dst1 : dst0;
            const unsigned int mbp = p ? mb1 : mb0;
            unsigned int ra, rm;
            asm volatile("mapa.shared::cluster.u32 %0, %1, %2;"
                         : "=r"(ra) : "r"(dl), "r"(t));
            asm volatile("mapa.shared::cluster.u32 %0, %1, %2;"
                         : "=r"(rm) : "r"(mbp), "r"(t));
            asm volatile(
                "cp.async.bulk.shared::cluster.shared::cta.mbarrier::complete_tx::bytes "
                "[%0], [%1], %2, [%3];"
                :: "r"(ra), "r"(src), "r"((unsigned int)(RBLK * 4)), "r"(rm)
                : "memory");
            asm volatile("cp.async.bulk.commit_group;" ::: "memory");
        }

        if (s == S_ - 1 && out_size >= B_ + B_ * H_)
            out[B_ + batch * H_ + row] = hv;   // hidden block of the output
    }

    // Final delivery (h_512, parity 0): completion index 255 -> phase 1.
    mbar_wait(mb0, 1);
    asm volatile("barrier.cluster.arrive.aligned;" ::: "memory");
    asm volatile("barrier.cluster.wait.aligned;"   ::: "memory");

    // Head: sig[b] = sigmoid(hidden[b] . Wf[0] + bf[0]); final h in hbuf[0]
    if (rt == 0) {
        float part = 0.0f;
        #pragma unroll
        for (int m = 0; m < 8; m++) {
            int k = r + 64 * m;                // row k, source rank m
            part += hbuf[0][m * RBLK + cb * 64 + r] * Wf[k];
        }
        red[t] = part;                         // t = r*4 + cb
        __syncthreads();
        for (int off = 32; off > 0; off >>= 1) {
            if (r < off) red[r * 4 + cb] += red[(r + off) * 4 + cb];
            __syncthreads();
        }
        if (r == 0)
            out[batch] = 1.0f / (1.0f + __expf(-(red[cb] + bf[0])));
    }
}

// ---------------------------------------------------------------------------
extern "C" void kernel_launch(void* const* d_in, const int* in_sizes, int n_in,
                              void* d_out, int out_size) {
    const int*   words = (const int*)d_in[0];   // int32 or int64 (auto-detected)
    const float* emb = (const float*)d_in[1];
    const float* Wh  = (const float*)d_in[2];
    const float* bh  = (const float*)d_in[3];
    const float* Wi  = (const float*)d_in[4];
    const float* bi  = (const float*)d_in[5];
    const float* Wf  = (const float*)d_in[6];
    const float* bf  = (const float*)d_in[7];
    float* out = (float*)d_out;

    dim3 gA(H_ / 64, (S_ * B_) / 64);          // (8, 512)
    xproj_kernel<<<gA, 256>>>(words, emb, Wi, bi);

    rnn_kernel<<<128, 256>>>(Wh, bh, Wf, bf, out, out_size);
}